// round 1
// baseline (speedup 1.0000x reference)
#include <cuda_runtime.h>
#include <cuda_bf16.h>
#include <math_constants.h>

// FixedMoiraiGating: logits = x @ W^T + b ; top-2 ; softmax over the 2 vals.
// x: [B*S=8192, D=4096] f32, W: [E=64, D=4096] f32, b: [64] f32
// out (f32, 32768): [0,16384)  = gate_probs  [token][k]
//                   [16384, 32768) = top-2 indices as float [token][k]

#define D_DIM 4096
#define E_DIM 64
#define BT 64      // tokens per block
#define BD 32      // D-chunk per smem stage
#define PITCH 68   // smem row pitch in floats (16B-aligned rows, bank-spread)

__global__ __launch_bounds__(256, 2)
void moirai_gating_kernel(const float* __restrict__ x,
                          const float* __restrict__ W,
                          const float* __restrict__ b,
                          float* __restrict__ out,
                          int n_tokens)
{
    __shared__ float xs[BD][PITCH];   // xs[d][token]
    __shared__ float ws[BD][PITCH];   // ws[d][expert]
    __shared__ float logits[BT][E_DIM + 1];

    const int tid  = threadIdx.x;
    const int tok0 = blockIdx.x * BT;

    // 16x16 thread grid over (token-groups, expert-groups), 4x4 register tile each
    const int ty = tid >> 4;   // 0..15 -> tokens ty*4 .. ty*4+3
    const int tx = tid & 15;   // 0..15 -> experts tx*4 .. tx*4+3

    float acc[4][4];
#pragma unroll
    for (int i = 0; i < 4; i++)
#pragma unroll
        for (int j = 0; j < 4; j++) acc[i][j] = 0.0f;

    // global-load mapping: each thread does one float4 per row-group, 2 row-groups
    const int lr = tid >> 3;          // 0..31 (row within tile)
    const int ld = (tid & 7) * 4;     // 0,4,...,28 (d offset within chunk)

    for (int d0 = 0; d0 < D_DIM; d0 += BD) {
#pragma unroll
        for (int it = 0; it < 2; it++) {
            const int r = lr + it * 32;  // 0..63
            // x tile: token r of this block
            float4 xv = *reinterpret_cast<const float4*>(
                x + (size_t)(tok0 + r) * D_DIM + d0 + ld);
            xs[ld + 0][r] = xv.x;
            xs[ld + 1][r] = xv.y;
            xs[ld + 2][r] = xv.z;
            xs[ld + 3][r] = xv.w;
            // W tile: expert r
            float4 wv = *reinterpret_cast<const float4*>(
                W + (size_t)r * D_DIM + d0 + ld);
            ws[ld + 0][r] = wv.x;
            ws[ld + 1][r] = wv.y;
            ws[ld + 2][r] = wv.z;
            ws[ld + 3][r] = wv.w;
        }
        __syncthreads();

#pragma unroll
        for (int kk = 0; kk < BD; kk++) {
            float4 xv = *reinterpret_cast<const float4*>(&xs[kk][ty * 4]);
            float4 wv = *reinterpret_cast<const float4*>(&ws[kk][tx * 4]);
            float xr[4] = {xv.x, xv.y, xv.z, xv.w};
            float wr[4] = {wv.x, wv.y, wv.z, wv.w};
#pragma unroll
            for (int i = 0; i < 4; i++)
#pragma unroll
                for (int j = 0; j < 4; j++)
                    acc[i][j] = fmaf(xr[i], wr[j], acc[i][j]);
        }
        __syncthreads();
    }

    // write logits (+bias) to smem
#pragma unroll
    for (int j = 0; j < 4; j++) {
        const float bj = __ldg(b + tx * 4 + j);
#pragma unroll
        for (int i = 0; i < 4; i++)
            logits[ty * 4 + i][tx * 4 + j] = acc[i][j] + bj;
    }
    __syncthreads();

    // top-2 + softmax, one thread per token
    if (tid < BT) {
        float v1 = -CUDART_INF_F, v2 = -CUDART_INF_F;
        int i1 = 0, i2 = 0;
#pragma unroll 8
        for (int e = 0; e < E_DIM; e++) {
            float v = logits[tid][e];
            if (v > v1) { v2 = v1; i2 = i1; v1 = v; i1 = e; }
            else if (v > v2) { v2 = v; i2 = e; }
        }
        float ex = expf(v2 - v1);       // <= 1, no overflow
        float inv = 1.0f / (1.0f + ex);
        float p1 = inv;
        float p2 = ex * inv;

        const int gt = tok0 + tid;
        out[gt * 2 + 0] = p1;
        out[gt * 2 + 1] = p2;
        float* idx_out = out + (size_t)n_tokens * 2;
        idx_out[gt * 2 + 0] = (float)i1;
        idx_out[gt * 2 + 1] = (float)i2;
    }
}

extern "C" void kernel_launch(void* const* d_in, const int* in_sizes, int n_in,
                              void* d_out, int out_size)
{
    const float* x = (const float*)d_in[0];
    const float* W = (const float*)d_in[1];
    const float* b = (const float*)d_in[2];
    float* out = (float*)d_out;

    const int n_tokens = in_sizes[0] / D_DIM;   // 8192
    const int grid = n_tokens / BT;             // 128

    moirai_gating_kernel<<<grid, 256>>>(x, W, b, out, n_tokens);
}

// round 5
// speedup vs baseline: 2.1967x; 2.1967x over previous
#include <cuda_runtime.h>
#include <cuda_fp16.h>
#include <math_constants.h>
#include <cstdint>

// FixedMoiraiGating: logits = x @ W^T + b ; top-2 ; softmax over the 2 vals.
// x: [8192, 4096] f32, W: [64, 4096] f32, b: [64] f32
// out f32[32768]: [0,16384) = probs [token][k]; [16384,32768) = indices as float.
//
// NOTE: harness compiles for plain sm_100 (no 'a') -> tcgen05 unavailable.
// Use portable warp-level mma.sync.m16n8k16 (f16 in, f32 acc), hi/lo split
// precision (3 terms: hh + hl + lh), which runs on Blackwell tensor cores.
//
// Kernel 1 (GEMM): 128 CTAs = 64 M-tiles x split-K 2. 128 threads = 4 warps,
//   warp tile m32 x n64. A path is register-direct (LDG.64 exactly the frag
//   elements, 2-kstep prefetch). B staged in smem fp16 hi/lo, ldmatrix frags.
//   Partials to __device__ scratch.
// Kernel 2: combine + bias + top-2 + softmax.

#define D_DIM  4096
#define E_DIM  64
#define BM     128
#define KHALF  2048
#define KC     64            // f32 k-elems per B stage (=128B fp16 rows)
#define NS     (KHALF / KC)  // 32 stages, 4 ksteps (k16) each
#define NKS    (KHALF / 16)  // 128 ksteps total
#define NTOK   8192

__device__ float g_scratch[2 * NTOK * E_DIM];   // 4MB split-K partials

#define MMA16816(c, a0, a1, a2, a3, b0, b1) \
    asm volatile("mma.sync.aligned.m16n8k16.row.col.f32.f16.f16.f32 " \
                 "{%0,%1,%2,%3}, {%4,%5,%6,%7}, {%8,%9}, {%0,%1,%2,%3};" \
                 : "+f"((c)[0]), "+f"((c)[1]), "+f"((c)[2]), "+f"((c)[3]) \
                 : "r"(a0), "r"(a1), "r"(a2), "r"(a3), "r"(b0), "r"(b1))

#define LDSM_X4(r0, r1, r2, r3, addr) \
    asm volatile("ldmatrix.sync.aligned.m8n8.x4.shared.b16 {%0,%1,%2,%3}, [%4];" \
                 : "=r"(r0), "=r"(r1), "=r"(r2), "=r"(r3) : "r"(addr))

static __device__ __forceinline__ uint32_t smem_u32(const void* p) {
    uint32_t a;
    asm("{ .reg .u64 t; cvta.to.shared.u64 t, %1; cvt.u32.u64 %0, t; }"
        : "=r"(a) : "l"(p));
    return a;
}

static __device__ __forceinline__ uint32_t h2u(__half2 h) {
    return *reinterpret_cast<uint32_t*>(&h);
}

// pack float2 -> (hi half2 as u32, lo residual half2 as u32)
static __device__ __forceinline__ void split2(float2 v, uint32_t& hi, uint32_t& lo) {
    __half2 h = __floats2half2_rn(v.x, v.y);
    float2 bk = __half22float2(h);
    __half2 l = __floats2half2_rn(v.x - bk.x, v.y - bk.y);
    hi = h2u(h);
    lo = h2u(l);
}

// B smem tile: [n=64 rows][128 bytes] with 128B swizzle: bits[6:4] ^= (n&7)<<4
static __device__ __forceinline__ uint32_t bswz(int n, uint32_t kbyte) {
    return (uint32_t)(n * 128) + (kbyte ^ (uint32_t)((n & 7) << 4));
}

// ---- GEMM kernel ----
__global__ __launch_bounds__(128, 1)
void moirai_gemm_kernel(const float* __restrict__ x,
                        const float* __restrict__ W)
{
    __shared__ __align__(1024) uint8_t sBh[2][8192];  // B hi, double buffered
    __shared__ __align__(1024) uint8_t sBl[2][8192];  // B lo

    const int t    = threadIdx.x;
    const int w    = t >> 5;
    const int lane = t & 31;
    const int tq   = lane >> 2;   // 0..7
    const int tr   = lane & 3;    // 0..3
    const int mt   = blockIdx.x & 63;
    const int kh   = blockIdx.x >> 6;
    const int tok0 = mt * BM;
    const int kb   = kh * KHALF;

    const uint32_t bh0 = smem_u32(&sBh[0][0]);
    const uint32_t bh1 = smem_u32(&sBh[1][0]);
    const uint32_t bl0 = smem_u32(&sBl[0][0]);
    const uint32_t bl1 = smem_u32(&sBl[1][0]);

    // ldmatrix lane addressing precompute (x4: lanes 0-7 -> matrix0 rows, ...)
    const int t7 = lane & 7;
    const int j  = lane >> 3;        // matrix index 0..3
    const int jp = j & 1;            // 0 = k[0:8), 1 = k[8:16)
    const int jh = j >> 1;           // 0 = n-tile q, 1 = n-tile q+1
    const uint32_t lanePart = (uint32_t)(jh * 1024 + t7 * 128);
    const uint32_t xorTerm  = (uint32_t)(t7 << 4);

    // accumulators: [mi][nt][4]
    float acc[2][8][4];
#pragma unroll
    for (int mi = 0; mi < 2; mi++)
#pragma unroll
        for (int nt = 0; nt < 8; nt++)
#pragma unroll
            for (int c = 0; c < 4; c++) acc[mi][nt][c] = 0.0f;

    // A row bases
    int rA[2];
    rA[0] = tok0 + w * 32 + tq;
    rA[1] = rA[0] + 16;

    // A prefetch ring, depth 2: af[slot][mi][j]
    // j: 0=(r, klo) 1=(r, khi) 2=(r+8, klo) 3=(r+8, khi)
    float2 af[2][2][4];

#define LOAD_A(slot, g) do {                                                  \
        int kc_ = kb + (g) * 16 + 2 * tr;                                     \
        _Pragma("unroll")                                                     \
        for (int mi_ = 0; mi_ < 2; mi_++) {                                   \
            const float* p0_ = x + (size_t)rA[mi_] * D_DIM + kc_;             \
            const float* p1_ = x + (size_t)(rA[mi_] + 8) * D_DIM + kc_;       \
            af[slot][mi_][0] = *reinterpret_cast<const float2*>(p0_);         \
            af[slot][mi_][1] = *reinterpret_cast<const float2*>(p0_ + 8);     \
            af[slot][mi_][2] = *reinterpret_cast<const float2*>(p1_);         \
            af[slot][mi_][3] = *reinterpret_cast<const float2*>(p1_ + 8);     \
        }                                                                     \
    } while (0)

    // B gmem staging regs: 8 float4 per thread per stage
    float4 bf4[8];
    int   brow[8], bc4[8];
#pragma unroll
    for (int i = 0; i < 8; i++) {
        int p = t + i * 128;
        brow[i] = p >> 4;       // expert 0..63
        bc4[i]  = p & 15;       // f4 index within 64-k row
    }

    // ---- preload: B stage 0 (load+convert+STS), A ksteps 0,1 ----
#pragma unroll
    for (int i = 0; i < 8; i++)
        bf4[i] = *reinterpret_cast<const float4*>(
            W + (size_t)brow[i] * D_DIM + kb + bc4[i] * 4);
    LOAD_A(0, 0);
    LOAD_A(1, 1);
#pragma unroll
    for (int i = 0; i < 8; i++) {
        uint32_t h0, l0, h1, l1;
        split2(make_float2(bf4[i].x, bf4[i].y), h0, l0);
        split2(make_float2(bf4[i].z, bf4[i].w), h1, l1);
        uint32_t off = bswz(brow[i], (uint32_t)(bc4[i] * 8));
        asm volatile("st.shared.v2.b32 [%0], {%1,%2};" :: "r"(bh0 + off), "r"(h0), "r"(h1) : "memory");
        asm volatile("st.shared.v2.b32 [%0], {%1,%2};" :: "r"(bl0 + off), "r"(l0), "r"(l1) : "memory");
    }
    __syncthreads();

    // ---- main loop ----
    for (int stage = 0; stage < NS; stage++) {
        const uint32_t curh = (stage & 1) ? bh1 : bh0;
        const uint32_t curl = (stage & 1) ? bl1 : bl0;
        const uint32_t nxth = (stage & 1) ? bh0 : bh1;
        const uint32_t nxtl = (stage & 1) ? bl0 : bl1;

        // issue B global loads for next stage
        if (stage + 1 < NS) {
            const int kbs = kb + (stage + 1) * KC;
#pragma unroll
            for (int i = 0; i < 8; i++)
                bf4[i] = *reinterpret_cast<const float4*>(
                    W + (size_t)brow[i] * D_DIM + kbs + bc4[i] * 4);
        }

#pragma unroll
        for (int ks = 0; ks < 4; ks++) {
            const int g = stage * 4 + ks;
            const int slot = g & 1;

            // 1) ldmatrix B frags for this kstep (latency overlapped below)
            uint32_t bhf[8][2], blf[8][2];
            const uint32_t kpart = ((uint32_t)(ks << 5) | (uint32_t)(jp << 4)) ^ xorTerm;
#pragma unroll
            for (int q = 0; q < 8; q += 2) {
                uint32_t ah_ = curh + (uint32_t)(q * 1024) + lanePart + kpart;
                uint32_t al_ = curl + (uint32_t)(q * 1024) + lanePart + kpart;
                LDSM_X4(bhf[q][0], bhf[q][1], bhf[q + 1][0], bhf[q + 1][1], ah_);
                LDSM_X4(blf[q][0], blf[q][1], blf[q + 1][0], blf[q + 1][1], al_);
            }

            // 2) convert prefetched A (loaded >=2 ksteps ago)
            uint32_t ah[2][4], al[2][4];
#pragma unroll
            for (int mi = 0; mi < 2; mi++)
#pragma unroll
                for (int jj = 0; jj < 4; jj++)
                    split2(af[slot][mi][jj], ah[mi][jj], al[mi][jj]);

            // 3) refill this slot with kstep g+2
            if (g + 2 < NKS) LOAD_A(slot, g + 2);

            // 4) 48 MMAs: hh + hl + lh
#pragma unroll
            for (int mi = 0; mi < 2; mi++) {
#pragma unroll
                for (int nt = 0; nt < 8; nt++) {
                    MMA16816(acc[mi][nt], ah[mi][0], ah[mi][2], ah[mi][1], ah[mi][3],
                             bhf[nt][0], bhf[nt][1]);
                    MMA16816(acc[mi][nt], ah[mi][0], ah[mi][2], ah[mi][1], ah[mi][3],
                             blf[nt][0], blf[nt][1]);
                    MMA16816(acc[mi][nt], al[mi][0], al[mi][2], al[mi][1], al[mi][3],
                             bhf[nt][0], bhf[nt][1]);
                }
            }
        }

        // convert + store next B stage
        if (stage + 1 < NS) {
#pragma unroll
            for (int i = 0; i < 8; i++) {
                uint32_t h0, l0, h1, l1;
                split2(make_float2(bf4[i].x, bf4[i].y), h0, l0);
                split2(make_float2(bf4[i].z, bf4[i].w), h1, l1);
                uint32_t off = bswz(brow[i], (uint32_t)(bc4[i] * 8));
                asm volatile("st.shared.v2.b32 [%0], {%1,%2};" :: "r"(nxth + off), "r"(h0), "r"(h1) : "memory");
                asm volatile("st.shared.v2.b32 [%0], {%1,%2};" :: "r"(nxtl + off), "r"(l0), "r"(l1) : "memory");
            }
        }
        __syncthreads();
    }

    // ---- epilogue: write partials to scratch ----
    // acc[mi][nt]: c0,c1 -> (row = rA[mi], col = nt*8 + 2*tr, +1)
    //              c2,c3 -> (row = rA[mi] + 8, same cols)
    float* sbase = g_scratch + (size_t)kh * NTOK * E_DIM;
#pragma unroll
    for (int mi = 0; mi < 2; mi++) {
#pragma unroll
        for (int nt = 0; nt < 8; nt++) {
            int col = nt * 8 + 2 * tr;
            float2 v0 = make_float2(acc[mi][nt][0], acc[mi][nt][1]);
            float2 v1 = make_float2(acc[mi][nt][2], acc[mi][nt][3]);
            *reinterpret_cast<float2*>(sbase + (size_t)rA[mi] * E_DIM + col) = v0;
            *reinterpret_cast<float2*>(sbase + (size_t)(rA[mi] + 8) * E_DIM + col) = v1;
        }
    }
}

// ---- combine + bias + top-2 + softmax ----
__global__ __launch_bounds__(256, 4)
void moirai_topk_kernel(const float* __restrict__ b,
                        float* __restrict__ out)
{
    const int t = blockIdx.x * 256 + threadIdx.x;
    const float* r0 = g_scratch + (size_t)t * E_DIM;
    const float* r1 = g_scratch + ((size_t)NTOK + t) * E_DIM;

    float v1 = -CUDART_INF_F, v2 = -CUDART_INF_F;
    int i1 = 0, i2 = 0;
#pragma unroll
    for (int g = 0; g < 16; g++) {
        float4 a  = *reinterpret_cast<const float4*>(r0 + g * 4);
        float4 c  = *reinterpret_cast<const float4*>(r1 + g * 4);
        float4 bb = *reinterpret_cast<const float4*>(b + g * 4);
        float v[4] = {a.x + c.x + bb.x, a.y + c.y + bb.y,
                      a.z + c.z + bb.z, a.w + c.w + bb.w};
#pragma unroll
        for (int jj = 0; jj < 4; jj++) {
            int e = g * 4 + jj;
            if (v[jj] > v1)      { v2 = v1; i2 = i1; v1 = v[jj]; i1 = e; }
            else if (v[jj] > v2) { v2 = v[jj]; i2 = e; }
        }
    }
    float ex  = expf(v2 - v1);
    float inv = 1.0f / (1.0f + ex);

    out[t * 2 + 0] = inv;
    out[t * 2 + 1] = ex * inv;
    float* idx_out = out + (size_t)NTOK * 2;
    idx_out[t * 2 + 0] = (float)i1;
    idx_out[t * 2 + 1] = (float)i2;
}

extern "C" void kernel_launch(void* const* d_in, const int* in_sizes, int n_in,
                              void* d_out, int out_size)
{
    const float* x = (const float*)d_in[0];
    const float* W = (const float*)d_in[1];
    const float* b = (const float*)d_in[2];
    float* out = (float*)d_out;

    moirai_gemm_kernel<<<128, 128>>>(x, W);
    moirai_topk_kernel<<<NTOK / 256, 256>>>(b, out);
}

// round 6
// speedup vs baseline: 3.0279x; 1.3784x over previous
#include <cuda_runtime.h>
#include <cuda_fp16.h>
#include <math_constants.h>
#include <cstdint>

// FixedMoiraiGating: logits = x @ W^T + b ; top-2 ; softmax over the 2 vals.
// x: [8192, 4096] f32, W: [64, 4096] f32, b: [64] f32
// out f32[32768]: [0,16384) = probs [token][k]; [16384,32768) = indices as float.
//
// Warp-level mma.sync m16n8k16 (plain sm_100 target: no tcgen05), fp16 hi/lo
// 3-term split precision (hh + hl + lh), fp32 accum.
// R6: 8 warps/CTA (2 per SMSP) for latency hiding, warp tile m16 x n64;
//     topk kernel spread over 128 CTAs.

#define D_DIM  4096
#define E_DIM  64
#define BM     128
#define KHALF  2048
#define KC     64            // f32 k-elems per B stage
#define NS     (KHALF / KC)  // 32 stages, 4 ksteps each
#define NKS    (KHALF / 16)  // 128 ksteps
#define NTOK   8192

__device__ float g_scratch[2 * NTOK * E_DIM];   // 4MB split-K partials

#define MMA16816(c, a0, a1, a2, a3, b0, b1) \
    asm volatile("mma.sync.aligned.m16n8k16.row.col.f32.f16.f16.f32 " \
                 "{%0,%1,%2,%3}, {%4,%5,%6,%7}, {%8,%9}, {%0,%1,%2,%3};" \
                 : "+f"((c)[0]), "+f"((c)[1]), "+f"((c)[2]), "+f"((c)[3]) \
                 : "r"(a0), "r"(a1), "r"(a2), "r"(a3), "r"(b0), "r"(b1))

#define LDSM_X4(r0, r1, r2, r3, addr) \
    asm volatile("ldmatrix.sync.aligned.m8n8.x4.shared.b16 {%0,%1,%2,%3}, [%4];" \
                 : "=r"(r0), "=r"(r1), "=r"(r2), "=r"(r3) : "r"(addr))

static __device__ __forceinline__ uint32_t smem_u32(const void* p) {
    uint32_t a;
    asm("{ .reg .u64 t; cvta.to.shared.u64 t, %1; cvt.u32.u64 %0, t; }"
        : "=r"(a) : "l"(p));
    return a;
}

static __device__ __forceinline__ uint32_t h2u(__half2 h) {
    return *reinterpret_cast<uint32_t*>(&h);
}

static __device__ __forceinline__ void split2(float2 v, uint32_t& hi, uint32_t& lo) {
    __half2 h = __floats2half2_rn(v.x, v.y);
    float2 bk = __half22float2(h);
    __half2 l = __floats2half2_rn(v.x - bk.x, v.y - bk.y);
    hi = h2u(h);
    lo = h2u(l);
}

// B smem: [n=64 rows][128 bytes], swizzle bits[6:4] ^= (n&7)<<4
static __device__ __forceinline__ uint32_t bswz(int n, uint32_t kbyte) {
    return (uint32_t)(n * 128) + (kbyte ^ (uint32_t)((n & 7) << 4));
}

__global__ __launch_bounds__(256, 1)
void moirai_gemm_kernel(const float* __restrict__ x,
                        const float* __restrict__ W)
{
    __shared__ __align__(1024) uint8_t sBh[2][8192];
    __shared__ __align__(1024) uint8_t sBl[2][8192];

    const int t    = threadIdx.x;
    const int w    = t >> 5;         // 0..7
    const int lane = t & 31;
    const int tq   = lane >> 2;
    const int tr   = lane & 3;
    const int mt   = blockIdx.x & 63;
    const int kh   = blockIdx.x >> 6;
    const int tok0 = mt * BM;
    const int kb   = kh * KHALF;

    const uint32_t bh0 = smem_u32(&sBh[0][0]);
    const uint32_t bh1 = smem_u32(&sBh[1][0]);
    const uint32_t bl0 = smem_u32(&sBl[0][0]);
    const uint32_t bl1 = smem_u32(&sBl[1][0]);

    const int t7 = lane & 7;
    const int j  = lane >> 3;
    const int jp = j & 1;
    const int jh = j >> 1;
    const uint32_t lanePart = (uint32_t)(jh * 1024 + t7 * 128);
    const uint32_t xorTerm  = (uint32_t)(t7 << 4);

    float acc[8][4];
#pragma unroll
    for (int nt = 0; nt < 8; nt++)
#pragma unroll
        for (int c = 0; c < 4; c++) acc[nt][c] = 0.0f;

    const int rA = tok0 + w * 16 + tq;     // warp tile m16

    // A prefetch ring depth 2: af[slot][j], j: 0=(r,klo) 1=(r,khi) 2=(r+8,klo) 3=(r+8,khi)
    float2 af[2][4];

#define LOAD_A(slot, g) do {                                            \
        int kc_ = kb + (g) * 16 + 2 * tr;                               \
        const float* p0_ = x + (size_t)rA * D_DIM + kc_;                \
        const float* p1_ = x + (size_t)(rA + 8) * D_DIM + kc_;          \
        af[slot][0] = *reinterpret_cast<const float2*>(p0_);            \
        af[slot][1] = *reinterpret_cast<const float2*>(p0_ + 8);        \
        af[slot][2] = *reinterpret_cast<const float2*>(p1_);            \
        af[slot][3] = *reinterpret_cast<const float2*>(p1_ + 8);        \
    } while (0)

    // B staging: 1024 float4/stage over 256 threads -> 4 per thread
    float4 bf4[4];
    int   brow[4], bc4[4];
#pragma unroll
    for (int i = 0; i < 4; i++) {
        int p = t + i * 256;
        brow[i] = p >> 4;
        bc4[i]  = p & 15;
    }

    // preload B stage 0 + A ksteps 0,1
#pragma unroll
    for (int i = 0; i < 4; i++)
        bf4[i] = *reinterpret_cast<const float4*>(
            W + (size_t)brow[i] * D_DIM + kb + bc4[i] * 4);
    LOAD_A(0, 0);
    LOAD_A(1, 1);
#pragma unroll
    for (int i = 0; i < 4; i++) {
        uint32_t h0, l0, h1, l1;
        split2(make_float2(bf4[i].x, bf4[i].y), h0, l0);
        split2(make_float2(bf4[i].z, bf4[i].w), h1, l1);
        uint32_t off = bswz(brow[i], (uint32_t)(bc4[i] * 8));
        asm volatile("st.shared.v2.b32 [%0], {%1,%2};" :: "r"(bh0 + off), "r"(h0), "r"(h1) : "memory");
        asm volatile("st.shared.v2.b32 [%0], {%1,%2};" :: "r"(bl0 + off), "r"(l0), "r"(l1) : "memory");
    }
    __syncthreads();

    for (int stage = 0; stage < NS; stage++) {
        const uint32_t curh = (stage & 1) ? bh1 : bh0;
        const uint32_t curl = (stage & 1) ? bl1 : bl0;
        const uint32_t nxth = (stage & 1) ? bh0 : bh1;
        const uint32_t nxtl = (stage & 1) ? bl0 : bl1;

        if (stage + 1 < NS) {
            const int kbs = kb + (stage + 1) * KC;
#pragma unroll
            for (int i = 0; i < 4; i++)
                bf4[i] = *reinterpret_cast<const float4*>(
                    W + (size_t)brow[i] * D_DIM + kbs + bc4[i] * 4);
        }

#pragma unroll
        for (int ks = 0; ks < 4; ks++) {
            const int g = stage * 4 + ks;
            const int slot = g & 1;

            uint32_t bhf[8][2], blf[8][2];
            const uint32_t kpart = ((uint32_t)(ks << 5) | (uint32_t)(jp << 4)) ^ xorTerm;
#pragma unroll
            for (int q = 0; q < 8; q += 2) {
                uint32_t ah_ = curh + (uint32_t)(q * 1024) + lanePart + kpart;
                uint32_t al_ = curl + (uint32_t)(q * 1024) + lanePart + kpart;
                LDSM_X4(bhf[q][0], bhf[q][1], bhf[q + 1][0], bhf[q + 1][1], ah_);
                LDSM_X4(blf[q][0], blf[q][1], blf[q + 1][0], blf[q + 1][1], al_);
            }

            uint32_t ah[4], al[4];
#pragma unroll
            for (int jj = 0; jj < 4; jj++)
                split2(af[slot][jj], ah[jj], al[jj]);

            if (g + 2 < NKS) LOAD_A(slot, g + 2);

#pragma unroll
            for (int nt = 0; nt < 8; nt++) {
                MMA16816(acc[nt], ah[0], ah[2], ah[1], ah[3], bhf[nt][0], bhf[nt][1]);
                MMA16816(acc[nt], ah[0], ah[2], ah[1], ah[3], blf[nt][0], blf[nt][1]);
                MMA16816(acc[nt], al[0], al[2], al[1], al[3], bhf[nt][0], bhf[nt][1]);
            }
        }

        if (stage + 1 < NS) {
#pragma unroll
            for (int i = 0; i < 4; i++) {
                uint32_t h0, l0, h1, l1;
                split2(make_float2(bf4[i].x, bf4[i].y), h0, l0);
                split2(make_float2(bf4[i].z, bf4[i].w), h1, l1);
                uint32_t off = bswz(brow[i], (uint32_t)(bc4[i] * 8));
                asm volatile("st.shared.v2.b32 [%0], {%1,%2};" :: "r"(nxth + off), "r"(h0), "r"(h1) : "memory");
                asm volatile("st.shared.v2.b32 [%0], {%1,%2};" :: "r"(nxtl + off), "r"(l0), "r"(l1) : "memory");
            }
        }
        __syncthreads();
    }

    // epilogue: partials to scratch
    float* sbase = g_scratch + (size_t)kh * NTOK * E_DIM;
#pragma unroll
    for (int nt = 0; nt < 8; nt++) {
        int col = nt * 8 + 2 * tr;
        *reinterpret_cast<float2*>(sbase + (size_t)rA * E_DIM + col) =
            make_float2(acc[nt][0], acc[nt][1]);
        *reinterpret_cast<float2*>(sbase + (size_t)(rA + 8) * E_DIM + col) =
            make_float2(acc[nt][2], acc[nt][3]);
    }
}

__global__ __launch_bounds__(64, 8)
void moirai_topk_kernel(const float* __restrict__ b,
                        float* __restrict__ out)
{
    const int t = blockIdx.x * 64 + threadIdx.x;
    const float* r0 = g_scratch + (size_t)t * E_DIM;
    const float* r1 = g_scratch + ((size_t)NTOK + t) * E_DIM;

    float v1 = -CUDART_INF_F, v2 = -CUDART_INF_F;
    int i1 = 0, i2 = 0;
#pragma unroll
    for (int g = 0; g < 16; g++) {
        float4 a  = *reinterpret_cast<const float4*>(r0 + g * 4);
        float4 c  = *reinterpret_cast<const float4*>(r1 + g * 4);
        float4 bb = *reinterpret_cast<const float4*>(b + g * 4);
        float v[4] = {a.x + c.x + bb.x, a.y + c.y + bb.y,
                      a.z + c.z + bb.z, a.w + c.w + bb.w};
#pragma unroll
        for (int jj = 0; jj < 4; jj++) {
            int e = g * 4 + jj;
            if (v[jj] > v1)      { v2 = v1; i2 = i1; v1 = v[jj]; i1 = e; }
            else if (v[jj] > v2) { v2 = v[jj]; i2 = e; }
        }
    }
    float ex  = expf(v2 - v1);
    float inv = 1.0f / (1.0f + ex);

    out[t * 2 + 0] = inv;
    out[t * 2 + 1] = ex * inv;
    float* idx_out = out + (size_t)NTOK * 2;
    idx_out[t * 2 + 0] = (float)i1;
    idx_out[t * 2 + 1] = (float)i2;
}

extern "C" void kernel_launch(void* const* d_in, const int* in_sizes, int n_in,
                              void* d_out, int out_size)
{
    const float* x = (const float*)d_in[0];
    const float* W = (const float*)d_in[1];
    const float* b = (const float*)d_in[2];
    float* out = (float*)d_out;

    moirai_gemm_kernel<<<128, 256>>>(x, W);
    moirai_topk_kernel<<<NTOK / 64, 64>>>(b, out);
}